// round 14
// baseline (speedup 1.0000x reference)
#include <cuda_runtime.h>

#define NN      4096
#define NBLK    1032          // 1024 pair-blocks + 8 diag-extra blocks
#define NFIN    16            // finalize blocks (the last 16 by blockIdx)

#define PED_SPEED   1.5f
#define ROBOT_SPEED 1.5f
#define K_ATTR      2.0f
#define ALPHA       10.0f
#define PED_RADIUS  0.3f
#define PED_MASS    60.0f
#define BETTA       0.71f
#define DT          0.4f
#define A_COST      4.0f
#define B_COST      1.2f
#define E_COST      0.001f
#define EPSF        1e-8f
#define LOG2E       1.4426950408889634f
#define LOG2_ALPHA  3.3219280948873623f   /* log2(10) */

#define C1C (-LOG2E / BETTA)
#define C0C ((2.0f * PED_RADIUS) * LOG2E / BETTA)
#define C0A (C0C + LOG2_ALPHA)            /* ALPHA folded into the exponent */

// All zero-initialized at module load. The last finalize block re-zeroes
// g_force and resets the counters at the end of every call, so the entry
// invariant holds for the correctness call AND for every graph replay.
__device__ float2 g_force[NN];
__device__ int    g_count;     // force-phase completion counter
__device__ int    g_count2;    // finalize-phase completion counter

__device__ __forceinline__ float ex2_approx(float x) {
    float r;
    asm("ex2.approx.ftz.f32 %0, %1;" : "=f"(r) : "f"(x));
    return r;
}
__device__ __forceinline__ float rsqrt_approx(float x) {
    float r;
    asm("rsqrt.approx.ftz.f32 %0, %1;" : "=f"(r) : "f"(x));
    return r;
}

// Single fused kernel:
//   entry (last 16 blocks): PREFETCH finalize inputs gmem->smem so the cold
//                           DRAM latency overlaps the force phase
//   phase A (blocks<1024):  distributed stacked-output copy
//   phase B (all blocks):   symmetric N^2 forces (Newton's 3rd law) -> REDG
//   phase C (last 16):      spin for g_count==NBLK, finalize from smem;
//                           last block zeroes g_force, resets counters.
__global__ void __launch_bounds__(256, 8) fused_kernel(
    const float4* __restrict__ state,
    const float*  __restrict__ cost_in,
    const float4* __restrict__ stacked_in,
    const float2* __restrict__ goals,
    const float*  __restrict__ robot_init,
    float4* __restrict__ out_state,
    float*  __restrict__ out_cost,
    float4* __restrict__ out_stacked)
{
    __shared__ float2 srow[8][32];
    __shared__ float4 sstate[256];
    __shared__ float2 sgoal[256];
    __shared__ float  scost[256];
    __shared__ float4 srob0;      // state[0]
    __shared__ float2 srobg;      // goals[0]
    __shared__ float2 srini;      // robot_init
    __shared__ int    slast;

    const int tid  = threadIdx.x;
    const int warp = tid >> 5;
    const int lane = tid & 31;
    const int b    = blockIdx.x;

    const bool isfin = (b >= NBLK - NFIN);
    const int  fb    = b - (NBLK - NFIN);     // finalize block id 0..15

    // ---- Entry prefetch (finalize blocks only): hide cold-DRAM latency ----
    if (isfin) {
        int i = fb * 256 + tid;
        sstate[tid] = state[i];
        sgoal[tid]  = goals[i];
        scost[tid]  = cost_in[i];
        if (tid == 0) {
            srob0 = state[0];
            srobg = goals[0];
            srini = make_float2(robot_init[0], robot_init[1]);
        }
    }

    // ---- Phase A: stacked copy, 8 float4 per block over blocks 0..1023 ----
    if (b < 1024 && tid < 8) {
        int idx = b * 8 + tid;                  // 0..8191
        out_stacked[idx] = (idx < NN) ? stacked_in[idx] : state[idx - NN];
    }

    // ---- Phase B: symmetric tile forces ----
    int  ti, tj;
    bool diag, extra;
    if (b < 1024) {
        ti = b >> 3;
        int s = ((b & 7) << 3) + warp + 1;      // s in 1..64
        diag  = (s == 64 && ti >= 64);          // reuse slot for diag 64..127
        extra = false;
        tj    = diag ? ti : ((ti + s) & 127);
    } else {
        ti    = ((b - 1024) << 3) + warp;       // diag tiles 0..63
        tj    = ti;
        diag  = true;
        extra = true;
    }
    const int I = ti << 5;
    const int J = tj << 5;

    const float4 sp = state[I + lane];
    const float pix = sp.x, piy = sp.y;

    float fix = 0.0f, fiy = 0.0f;

    if (!diag) {
        // Symmetric tile: row accum in regs, column accum rotates via shfl.
        float fcx = 0.0f, fcy = 0.0f;
        int c = lane;
        #pragma unroll 8
        for (int t = 0; t < 32; t++) {
            float4 q  = state[J + c];
            float dx  = pix - q.x;
            float dy  = piy - q.y;
            float s2  = fmaf(dx, dx, fmaf(dy, dy, EPSF));
            float rin = rsqrt_approx(s2);
            float m   = ex2_approx(fmaf(s2 * rin, C1C, C0A));
            float f   = m * rin;
            fix = fmaf(f, dx, fix);
            fiy = fmaf(f, dy, fiy);
            fcx = fmaf(f, dx, fcx);             // negated at the end
            fcy = fmaf(f, dy, fcy);
            fcx = __shfl_sync(0xffffffffu, fcx, (lane + 1) & 31);
            fcy = __shfl_sync(0xffffffffu, fcy, (lane + 1) & 31);
            c = (c + 1) & 31;
        }
        atomicAdd(&g_force[J + lane].x, -fcx);
        atomicAdd(&g_force[J + lane].y, -fcy);
    } else {
        // Diagonal tile: one-sided (self-pair is exactly 0).
        int c = lane;
        #pragma unroll 8
        for (int t = 0; t < 32; t++) {
            float4 q  = state[J + c];
            float dx  = pix - q.x;
            float dy  = piy - q.y;
            float s2  = fmaf(dx, dx, fmaf(dy, dy, EPSF));
            float rin = rsqrt_approx(s2);
            float m   = ex2_approx(fmaf(s2 * rin, C1C, C0A));
            float f   = m * rin;
            fix = fmaf(f, dx, fix);
            fiy = fmaf(f, dy, fiy);
            c = (c + 1) & 31;
        }
    }

    if (extra) {
        atomicAdd(&g_force[I + lane].x, fix);
        atomicAdd(&g_force[I + lane].y, fiy);
    } else {
        srow[warp][lane] = make_float2(fix, fiy);
        __syncthreads();
        if (warp == 0) {
            float sx = 0.0f, sy = 0.0f;
            #pragma unroll
            for (int w = 0; w < 8; w++) {
                sx += srow[w][lane].x;
                sy += srow[w][lane].y;
            }
            atomicAdd(&g_force[I + lane].x, sx);
            atomicAdd(&g_force[I + lane].y, sy);
        }
    }

    // ---- Signal force completion ----
    __syncthreads();
    if (tid == 0) {
        __threadfence();
        atomicAdd(&g_count, 1);
    }

    if (!isfin) return;

    // ---- Phase C: wait, then finalize from prefetched smem ----
    if (tid == 0) {
        while (*(volatile int*)&g_count < NBLK) __nanosleep(32);
    }
    __syncthreads();
    __threadfence();

    const int i = fb * 256 + tid;

    // Robot (row 0) pose + PG — from smem + L2-warm g_force[0].
    float2 gf0 = g_force[0];
    float4 s0  = srob0;
    float2 g0  = srobg;
    float r0x, r0y, PG;
    {
        float tgx  = g0.x - s0.x;
        float tgy  = g0.y - s0.y;
        float dist = sqrtf(fmaf(tgx, tgx, tgy * tgy));
        float einv = 1.0f / (dist + EPSF);
        float Fx   = gf0.x + K_ATTR * (ROBOT_SPEED * tgx * einv - s0.z) * PED_MASS;
        float Fy   = gf0.y + K_ATTR * (ROBOT_SPEED * tgy * einv - s0.w) * PED_MASS;
        float vnx   = fmaf(Fx, DT / PED_MASS, s0.z);
        float vny   = fmaf(Fy, DT / PED_MASS, s0.w);
        float speed = sqrtf(fmaf(vnx, vnx, vny * vny));
        float sc    = fminf(1.0f, PED_SPEED / (speed + EPSF));
        vnx *= sc; vny *= sc;
        r0x = fmaf(vnx, DT, s0.x);
        r0y = fmaf(vny, DT, s0.y);
        float gx  = g0.x - srini.x;
        float gy  = g0.y - srini.y;
        PG = (gx * (r0x - srini.x) + gy * (r0y - srini.y)) /
             (sqrtf(fmaf(gx, gx, gy * gy)) + E_COST);
    }

    // Own row — all inputs already in smem; only g_force[i] hits L2.
    float2 gf = g_force[i];
    float4 sr = sstate[tid];
    float2 g  = sgoal[tid];
    float tgx  = g.x - sr.x;
    float tgy  = g.y - sr.y;
    float dist = sqrtf(fmaf(tgx, tgx, tgy * tgy));
    float einv = 1.0f / (dist + EPSF);
    float ds   = (i == 0) ? ROBOT_SPEED : PED_SPEED;
    float Fx   = gf.x + K_ATTR * (ds * tgx * einv - sr.z) * PED_MASS;
    float Fy   = gf.y + K_ATTR * (ds * tgy * einv - sr.w) * PED_MASS;

    float vnx   = fmaf(Fx, DT / PED_MASS, sr.z);
    float vny   = fmaf(Fy, DT / PED_MASS, sr.w);
    float speed = sqrtf(fmaf(vnx, vnx, vny * vny));
    float sc    = fminf(1.0f, PED_SPEED / (speed + EPSF));
    vnx *= sc; vny *= sc;
    float pnx = fmaf(vnx, DT, sr.x);
    float pny = fmaf(vny, DT, sr.y);
    out_state[i] = make_float4(pnx, pny, vnx, vny);

    float ddx = pnx - r0x;
    float ddy = pny - r0y;
    float dr  = sqrtf(fmaf(ddx, ddx, fmaf(ddy, ddy, E_COST)));
    float blame = (i == 0) ? 0.0f : ex2_approx(-dr * (LOG2E / B_COST));
    out_cost[i] = scost[tid] + (-A_COST * PG + blame);

    // ---- Cleanup by the LAST finalize block only (after all reads done) ----
    __syncthreads();
    if (tid == 0) slast = (atomicAdd(&g_count2, 1) == NFIN - 1) ? 1 : 0;
    __syncthreads();
    if (slast) {
        for (int k = tid; k < NN; k += 256)
            g_force[k] = make_float2(0.0f, 0.0f);
        __syncthreads();
        if (tid == 0) {
            g_count = 0;
            __threadfence();
            g_count2 = 0;
        }
    }
}

extern "C" void kernel_launch(void* const* d_in, const int* in_sizes, int n_in,
                              void* d_out, int out_size)
{
    const float4* state   = (const float4*)d_in[0];
    const float*  cost    = (const float*)d_in[1];
    const float4* stacked = (const float4*)d_in[2];
    const float2* goals   = (const float2*)d_in[3];
    const float*  rinit   = (const float*)d_in[4];

    float*  out         = (float*)d_out;
    float4* out_state   = (float4*)out;            // [0, 4N)
    float*  out_cost    = out + 4 * NN;            // [4N, 5N)
    float4* out_stacked = (float4*)(out + 5 * NN); // [5N, 13N)

    fused_kernel<<<NBLK, 256>>>(state, cost, stacked, goals, rinit,
                                out_state, out_cost, out_stacked);
}

// round 15
// speedup vs baseline: 1.0171x; 1.0171x over previous
#include <cuda_runtime.h>

#define NN      4096
#define NBLK    1032          // 1024 pair-blocks + 8 diag-extra blocks

#define PED_SPEED   1.5f
#define ROBOT_SPEED 1.5f
#define K_ATTR      2.0f
#define ALPHA       10.0f
#define PED_RADIUS  0.3f
#define PED_MASS    60.0f
#define BETTA       0.71f
#define DT          0.4f
#define A_COST      4.0f
#define B_COST      1.2f
#define E_COST      0.001f
#define EPSF        1e-8f
#define LOG2E       1.4426950408889634f
#define LOG2_ALPHA  3.3219280948873623f   /* log2(10) */

#define C1C (-LOG2E / BETTA)
#define C0C ((2.0f * PED_RADIUS) * LOG2E / BETTA)
#define C0A (C0C + LOG2_ALPHA)            /* ALPHA folded into the exponent */

// Zero-initialized at module load. finalize_kernel (single block) re-zeroes
// it after a __syncthreads() that orders all reads before any zeroing, so the
// entry invariant holds for the correctness call AND every graph replay.
__device__ float2 g_force[NN];

__device__ __forceinline__ float ex2_approx(float x) {
    float r;
    asm("ex2.approx.ftz.f32 %0, %1;" : "=f"(r) : "f"(x));
    return r;
}
__device__ __forceinline__ float rsqrt_approx(float x) {
    float r;
    asm("rsqrt.approx.ftz.f32 %0, %1;" : "=f"(r) : "f"(x));
    return r;
}

// Symmetric N^2 forces: each unordered pair computed ONCE (Newton's 3rd law).
// 32x32 warp-tiles; column accumulator rotates via shfl; REDG accumulation.
// Also performs the stacked-output copy (distributed, overlaps compute).
__global__ void __launch_bounds__(256, 8) force_kernel(
    const float4* __restrict__ state,
    const float4* __restrict__ stacked_in,
    float4* __restrict__ out_stacked)
{
    __shared__ float2 srow[8][32];

    const int tid  = threadIdx.x;
    const int warp = tid >> 5;
    const int lane = tid & 31;
    const int b    = blockIdx.x;

    // ---- Stacked copy: 8 float4 per block over blocks 0..1023 ----
    if (b < 1024 && tid < 8) {
        int idx = b * 8 + tid;                  // 0..8191
        out_stacked[idx] = (idx < NN) ? stacked_in[idx] : state[idx - NN];
    }

    // ---- Symmetric tile forces ----
    int  ti, tj;
    bool diag, extra;
    if (b < 1024) {
        ti = b >> 3;
        int s = ((b & 7) << 3) + warp + 1;      // s in 1..64
        diag  = (s == 64 && ti >= 64);          // reuse slot for diag 64..127
        extra = false;
        tj    = diag ? ti : ((ti + s) & 127);
    } else {
        ti    = ((b - 1024) << 3) + warp;       // diag tiles 0..63
        tj    = ti;
        diag  = true;
        extra = true;
    }
    const int I = ti << 5;
    const int J = tj << 5;

    const float4 sp = state[I + lane];
    const float pix = sp.x, piy = sp.y;

    float fix = 0.0f, fiy = 0.0f;

    if (!diag) {
        // Symmetric tile: row accum in regs, column accum rotates via shfl.
        float fcx = 0.0f, fcy = 0.0f;
        int c = lane;
        #pragma unroll 8
        for (int t = 0; t < 32; t++) {
            float4 q  = state[J + c];
            float dx  = pix - q.x;
            float dy  = piy - q.y;
            float s2  = fmaf(dx, dx, fmaf(dy, dy, EPSF));
            float rin = rsqrt_approx(s2);
            float m   = ex2_approx(fmaf(s2 * rin, C1C, C0A));
            float f   = m * rin;
            fix = fmaf(f, dx, fix);
            fiy = fmaf(f, dy, fiy);
            fcx = fmaf(f, dx, fcx);             // negated at the end
            fcy = fmaf(f, dy, fcy);
            fcx = __shfl_sync(0xffffffffu, fcx, (lane + 1) & 31);
            fcy = __shfl_sync(0xffffffffu, fcy, (lane + 1) & 31);
            c = (c + 1) & 31;
        }
        atomicAdd(&g_force[J + lane].x, -fcx);
        atomicAdd(&g_force[J + lane].y, -fcy);
    } else {
        // Diagonal tile: one-sided (self-pair is exactly 0).
        int c = lane;
        #pragma unroll 8
        for (int t = 0; t < 32; t++) {
            float4 q  = state[J + c];
            float dx  = pix - q.x;
            float dy  = piy - q.y;
            float s2  = fmaf(dx, dx, fmaf(dy, dy, EPSF));
            float rin = rsqrt_approx(s2);
            float m   = ex2_approx(fmaf(s2 * rin, C1C, C0A));
            float f   = m * rin;
            fix = fmaf(f, dx, fix);
            fiy = fmaf(f, dy, fiy);
            c = (c + 1) & 31;
        }
    }

    if (extra) {
        atomicAdd(&g_force[I + lane].x, fix);
        atomicAdd(&g_force[I + lane].y, fiy);
    } else {
        srow[warp][lane] = make_float2(fix, fiy);
        __syncthreads();
        if (warp == 0) {
            float sx = 0.0f, sy = 0.0f;
            #pragma unroll
            for (int w = 0; w < 8; w++) {
                sx += srow[w][lane].x;
                sy += srow[w][lane].y;
            }
            atomicAdd(&g_force[I + lane].x, sx);
            atomicAdd(&g_force[I + lane].y, sy);
        }
    }
}

// Finalize: ONE block x 1024 threads (4 rows/thread). All cross-thread
// ordering handled by a single __syncthreads(): reads (incl. g_force[0]
// for the robot pose) happen before any zeroing. No counters, no races.
__global__ void __launch_bounds__(1024) finalize_kernel(
    const float4* __restrict__ state,
    const float*  __restrict__ cost_in,
    const float2* __restrict__ goals,
    const float*  __restrict__ robot_init,
    float4* __restrict__ out_state,
    float*  __restrict__ out_cost)
{
    const int tid = threadIdx.x;

    // ---- Robot (row 0) pose + PG (uniform; broadcast loads) ----
    float2 gf0 = g_force[0];
    float4 s0  = state[0];
    float2 g0  = goals[0];
    float rix  = robot_init[0];
    float riy  = robot_init[1];
    float r0x, r0y, PG;
    {
        float tgx  = g0.x - s0.x;
        float tgy  = g0.y - s0.y;
        float dist = sqrtf(fmaf(tgx, tgx, tgy * tgy));
        float einv = 1.0f / (dist + EPSF);
        float Fx   = gf0.x + K_ATTR * (ROBOT_SPEED * tgx * einv - s0.z) * PED_MASS;
        float Fy   = gf0.y + K_ATTR * (ROBOT_SPEED * tgy * einv - s0.w) * PED_MASS;
        float vnx   = fmaf(Fx, DT / PED_MASS, s0.z);
        float vny   = fmaf(Fy, DT / PED_MASS, s0.w);
        float speed = sqrtf(fmaf(vnx, vnx, vny * vny));
        float sc    = fminf(1.0f, PED_SPEED / (speed + EPSF));
        vnx *= sc; vny *= sc;
        r0x = fmaf(vnx, DT, s0.x);
        r0y = fmaf(vny, DT, s0.y);
        float gx = g0.x - rix;
        float gy = g0.y - riy;
        PG = (gx * (r0x - rix) + gy * (r0y - riy)) /
             (sqrtf(fmaf(gx, gx, gy * gy)) + E_COST);
    }

    // ---- Own rows: 4 per thread ----
    #pragma unroll
    for (int k = 0; k < NN / 1024; k++) {
        int i = tid + k * 1024;
        float2 gf = g_force[i];
        float4 sr = state[i];
        float2 g  = goals[i];
        float ci  = cost_in[i];

        float tgx  = g.x - sr.x;
        float tgy  = g.y - sr.y;
        float dist = sqrtf(fmaf(tgx, tgx, tgy * tgy));
        float einv = 1.0f / (dist + EPSF);
        float ds   = (i == 0) ? ROBOT_SPEED : PED_SPEED;
        float Fx   = gf.x + K_ATTR * (ds * tgx * einv - sr.z) * PED_MASS;
        float Fy   = gf.y + K_ATTR * (ds * tgy * einv - sr.w) * PED_MASS;

        float vnx   = fmaf(Fx, DT / PED_MASS, sr.z);
        float vny   = fmaf(Fy, DT / PED_MASS, sr.w);
        float speed = sqrtf(fmaf(vnx, vnx, vny * vny));
        float sc    = fminf(1.0f, PED_SPEED / (speed + EPSF));
        vnx *= sc; vny *= sc;
        float pnx = fmaf(vnx, DT, sr.x);
        float pny = fmaf(vny, DT, sr.y);
        out_state[i] = make_float4(pnx, pny, vnx, vny);

        float ddx = pnx - r0x;
        float ddy = pny - r0y;
        float dr  = sqrtf(fmaf(ddx, ddx, fmaf(ddy, ddy, E_COST)));
        float blame = (i == 0) ? 0.0f : ex2_approx(-dr * (LOG2E / B_COST));
        out_cost[i] = ci + (-A_COST * PG + blame);
    }

    // ---- Reset accumulators for the next graph replay ----
    __syncthreads();     // all reads (incl. g_force[0]) complete before zeroing
    #pragma unroll
    for (int k = 0; k < NN / 1024; k++)
        g_force[tid + k * 1024] = make_float2(0.0f, 0.0f);
}

extern "C" void kernel_launch(void* const* d_in, const int* in_sizes, int n_in,
                              void* d_out, int out_size)
{
    const float4* state   = (const float4*)d_in[0];
    const float*  cost    = (const float*)d_in[1];
    const float4* stacked = (const float4*)d_in[2];
    const float2* goals   = (const float2*)d_in[3];
    const float*  rinit   = (const float*)d_in[4];

    float*  out         = (float*)d_out;
    float4* out_state   = (float4*)out;            // [0, 4N)
    float*  out_cost    = out + 4 * NN;            // [4N, 5N)
    float4* out_stacked = (float4*)(out + 5 * NN); // [5N, 13N)

    force_kernel<<<NBLK, 256>>>(state, stacked, out_stacked);
    finalize_kernel<<<1, 1024>>>(state, cost, goals, rinit,
                                 out_state, out_cost);
}

// round 16
// speedup vs baseline: 1.1380x; 1.1189x over previous
#include <cuda_runtime.h>

#define NN      4096
#define NBLK    1032          // 1024 pair-blocks + 8 diag-extra blocks
#define NFIN    16            // finalize blocks

#define PED_SPEED   1.5f
#define ROBOT_SPEED 1.5f
#define K_ATTR      2.0f
#define ALPHA       10.0f
#define PED_RADIUS  0.3f
#define PED_MASS    60.0f
#define BETTA       0.71f
#define DT          0.4f
#define A_COST      4.0f
#define B_COST      1.2f
#define E_COST      0.001f
#define EPSF        1e-8f
#define LOG2E       1.4426950408889634f
#define LOG2_ALPHA  3.3219280948873623f   /* log2(10) */

#define C1C (-LOG2E / BETTA)
#define C0C ((2.0f * PED_RADIUS) * LOG2E / BETTA)
#define C0A (C0C + LOG2_ALPHA)            /* ALPHA folded into the exponent */

// Zero-initialized at module load. finalize_kernel restores the all-zero
// state every call: each block zeroes its own row range after its reads;
// row 0 (read by every block) is zeroed by the LAST block to pass its read
// point (detected via g_fin). Replay-safe, no spin waits.
__device__ float2 g_force[NN];
__device__ int    g_fin;

__device__ __forceinline__ float ex2_approx(float x) {
    float r;
    asm("ex2.approx.ftz.f32 %0, %1;" : "=f"(r) : "f"(x));
    return r;
}
__device__ __forceinline__ float rsqrt_approx(float x) {
    float r;
    asm("rsqrt.approx.ftz.f32 %0, %1;" : "=f"(r) : "f"(x));
    return r;
}

// Symmetric N^2 forces: each unordered pair computed ONCE (Newton's 3rd law).
// 32x32 warp-tiles; column accumulator rotates via shfl; REDG accumulation.
// Also performs the stacked-output copy (distributed, overlaps compute).
__global__ void __launch_bounds__(256, 8) force_kernel(
    const float4* __restrict__ state,
    const float4* __restrict__ stacked_in,
    float4* __restrict__ out_stacked)
{
    __shared__ float2 srow[8][32];

    const int tid  = threadIdx.x;
    const int warp = tid >> 5;
    const int lane = tid & 31;
    const int b    = blockIdx.x;

    // ---- Stacked copy: 8 float4 per block over blocks 0..1023 ----
    if (b < 1024 && tid < 8) {
        int idx = b * 8 + tid;                  // 0..8191
        out_stacked[idx] = (idx < NN) ? stacked_in[idx] : state[idx - NN];
    }

    // ---- Symmetric tile forces ----
    int  ti, tj;
    bool diag, extra;
    if (b < 1024) {
        ti = b >> 3;
        int s = ((b & 7) << 3) + warp + 1;      // s in 1..64
        diag  = (s == 64 && ti >= 64);          // reuse slot for diag 64..127
        extra = false;
        tj    = diag ? ti : ((ti + s) & 127);
    } else {
        ti    = ((b - 1024) << 3) + warp;       // diag tiles 0..63
        tj    = ti;
        diag  = true;
        extra = true;
    }
    const int I = ti << 5;
    const int J = tj << 5;

    const float4 sp = state[I + lane];
    const float pix = sp.x, piy = sp.y;

    float fix = 0.0f, fiy = 0.0f;

    if (!diag) {
        // Symmetric tile: row accum in regs, column accum rotates via shfl.
        float fcx = 0.0f, fcy = 0.0f;
        int c = lane;
        #pragma unroll 8
        for (int t = 0; t < 32; t++) {
            float4 q  = state[J + c];
            float dx  = pix - q.x;
            float dy  = piy - q.y;
            float s2  = fmaf(dx, dx, fmaf(dy, dy, EPSF));
            float rin = rsqrt_approx(s2);
            float m   = ex2_approx(fmaf(s2 * rin, C1C, C0A));
            float f   = m * rin;
            fix = fmaf(f, dx, fix);
            fiy = fmaf(f, dy, fiy);
            fcx = fmaf(f, dx, fcx);             // negated at the end
            fcy = fmaf(f, dy, fcy);
            fcx = __shfl_sync(0xffffffffu, fcx, (lane + 1) & 31);
            fcy = __shfl_sync(0xffffffffu, fcy, (lane + 1) & 31);
            c = (c + 1) & 31;
        }
        atomicAdd(&g_force[J + lane].x, -fcx);
        atomicAdd(&g_force[J + lane].y, -fcy);
    } else {
        // Diagonal tile: one-sided (self-pair is exactly 0).
        int c = lane;
        #pragma unroll 8
        for (int t = 0; t < 32; t++) {
            float4 q  = state[J + c];
            float dx  = pix - q.x;
            float dy  = piy - q.y;
            float s2  = fmaf(dx, dx, fmaf(dy, dy, EPSF));
            float rin = rsqrt_approx(s2);
            float m   = ex2_approx(fmaf(s2 * rin, C1C, C0A));
            float f   = m * rin;
            fix = fmaf(f, dx, fix);
            fiy = fmaf(f, dy, fiy);
            c = (c + 1) & 31;
        }
    }

    if (extra) {
        atomicAdd(&g_force[I + lane].x, fix);
        atomicAdd(&g_force[I + lane].y, fiy);
    } else {
        srow[warp][lane] = make_float2(fix, fiy);
        __syncthreads();
        if (warp == 0) {
            float sx = 0.0f, sy = 0.0f;
            #pragma unroll
            for (int w = 0; w < 8; w++) {
                sx += srow[w][lane].x;
                sy += srow[w][lane].y;
            }
            atomicAdd(&g_force[I + lane].x, sx);
            atomicAdd(&g_force[I + lane].y, sy);
        }
    }
}

// Finalize: 16 blocks x 256 threads, ONE row per thread. All per-row loads
// are independent and issued up front (high MLP). Cleanup: each block zeroes
// its own rows post-read; row 0 is zeroed by the last block through g_fin.
__global__ void __launch_bounds__(256) finalize_kernel(
    const float4* __restrict__ state,
    const float*  __restrict__ cost_in,
    const float2* __restrict__ goals,
    const float*  __restrict__ robot_init,
    float4* __restrict__ out_state,
    float*  __restrict__ out_cost)
{
    const int tid = threadIdx.x;
    const int i   = blockIdx.x * 256 + tid;

    // ---- Issue ALL loads up front (independent -> one latency round) ----
    float2 gf  = g_force[i];
    float4 sr  = state[i];
    float2 g   = goals[i];
    float  ci  = cost_in[i];
    float2 gf0 = g_force[0];      // broadcast
    float4 s0  = state[0];
    float2 g0  = goals[0];
    float  rix = robot_init[0];
    float  riy = robot_init[1];

    // ---- Robot (row 0) pose + PG ----
    float r0x, r0y, PG;
    {
        float tgx  = g0.x - s0.x;
        float tgy  = g0.y - s0.y;
        float dist = sqrtf(fmaf(tgx, tgx, tgy * tgy));
        float einv = 1.0f / (dist + EPSF);
        float Fx   = gf0.x + K_ATTR * (ROBOT_SPEED * tgx * einv - s0.z) * PED_MASS;
        float Fy   = gf0.y + K_ATTR * (ROBOT_SPEED * tgy * einv - s0.w) * PED_MASS;
        float vnx   = fmaf(Fx, DT / PED_MASS, s0.z);
        float vny   = fmaf(Fy, DT / PED_MASS, s0.w);
        float speed = sqrtf(fmaf(vnx, vnx, vny * vny));
        float sc    = fminf(1.0f, PED_SPEED / (speed + EPSF));
        vnx *= sc; vny *= sc;
        r0x = fmaf(vnx, DT, s0.x);
        r0y = fmaf(vny, DT, s0.y);
        float gx = g0.x - rix;
        float gy = g0.y - riy;
        PG = (gx * (r0x - rix) + gy * (r0y - riy)) /
             (sqrtf(fmaf(gx, gx, gy * gy)) + E_COST);
    }

    // ---- Own row ----
    float tgx  = g.x - sr.x;
    float tgy  = g.y - sr.y;
    float dist = sqrtf(fmaf(tgx, tgx, tgy * tgy));
    float einv = 1.0f / (dist + EPSF);
    float ds   = (i == 0) ? ROBOT_SPEED : PED_SPEED;
    float Fx   = gf.x + K_ATTR * (ds * tgx * einv - sr.z) * PED_MASS;
    float Fy   = gf.y + K_ATTR * (ds * tgy * einv - sr.w) * PED_MASS;

    float vnx   = fmaf(Fx, DT / PED_MASS, sr.z);
    float vny   = fmaf(Fy, DT / PED_MASS, sr.w);
    float speed = sqrtf(fmaf(vnx, vnx, vny * vny));
    float sc    = fminf(1.0f, PED_SPEED / (speed + EPSF));
    vnx *= sc; vny *= sc;
    float pnx = fmaf(vnx, DT, sr.x);
    float pny = fmaf(vny, DT, sr.y);
    out_state[i] = make_float4(pnx, pny, vnx, vny);

    float ddx = pnx - r0x;
    float ddy = pny - r0y;
    float dr  = sqrtf(fmaf(ddx, ddx, fmaf(ddy, ddy, E_COST)));
    float blame = (i == 0) ? 0.0f : ex2_approx(-dr * (LOG2E / B_COST));
    out_cost[i] = ci + (-A_COST * PG + blame);

    // ---- Cleanup for the next graph replay ----
    __syncthreads();                 // this block's reads are done
    if (i != 0)
        g_force[i] = make_float2(0.0f, 0.0f);   // own rows (row 0 excluded)
    __syncthreads();
    if (tid == 0) {
        // Last block through here knows every block finished its reads.
        if (atomicAdd(&g_fin, 1) == NFIN - 1) {
            g_force[0] = make_float2(0.0f, 0.0f);
            __threadfence();
            g_fin = 0;
        }
    }
}

extern "C" void kernel_launch(void* const* d_in, const int* in_sizes, int n_in,
                              void* d_out, int out_size)
{
    const float4* state   = (const float4*)d_in[0];
    const float*  cost    = (const float*)d_in[1];
    const float4* stacked = (const float4*)d_in[2];
    const float2* goals   = (const float2*)d_in[3];
    const float*  rinit   = (const float*)d_in[4];

    float*  out         = (float*)d_out;
    float4* out_state   = (float4*)out;            // [0, 4N)
    float*  out_cost    = out + 4 * NN;            // [4N, 5N)
    float4* out_stacked = (float4*)(out + 5 * NN); // [5N, 13N)

    force_kernel<<<NBLK, 256>>>(state, stacked, out_stacked);
    finalize_kernel<<<NFIN, 256>>>(state, cost, goals, rinit,
                                   out_state, out_cost);
}